// round 15
// baseline (speedup 1.0000x reference)
#include <cuda_runtime.h>
#include <cstdint>

typedef unsigned long long ull;

#define BATCH 256
#define NNODE 79
#define HID 256
#define NEDGE 3000
#define KP1 104
#define NROWS (BATCH*NNODE)     // 20224
#define MROWS 64                // qkvs rows/CTA
#define MLPR 32                 // mlp rows/CTA
#define NCH 24
#define CHSZ 125
#define NCELL (NNODE*NCH)

// ---------------- device scratch ----------------
__device__ int   g_srcp[NEDGE];
__device__ float g_ewp[NEDGE];
__device__ int   g_rowptr[NNODE + 1];
__device__ ull   g_W4D[32 * 256];        // k-major stacked q|k|v|skip, f32x2-dup (qkvs)
__device__ float g_W1U[KP1 * HID];       // k-major (mlp panels)
__device__ float g_W2U[HID * HID];
__device__ float g_q[(size_t)NROWS * 64];
__device__ float g_k[(size_t)NROWS * 64];
__device__ float g_v[(size_t)NROWS * 64];
__device__ float g_hin[(size_t)NROWS * KP1];
__device__ float g_conc[NROWS];

__device__ __forceinline__ float wredsum(float v) {
    #pragma unroll
    for (int o = 16; o; o >>= 1) v += __shfl_xor_sync(0xffffffffu, v, o);
    return v;
}
__device__ __forceinline__ float wredmax(float v) {
    #pragma unroll
    for (int o = 16; o; o >>= 1) v = fmaxf(v, __shfl_xor_sync(0xffffffffu, v, o));
    return v;
}
__device__ __forceinline__ ull dup2(float v) {
    ull r; asm("mov.b64 %0,{%1,%1};" : "=l"(r) : "f"(v)); return r;
}
__device__ __forceinline__ ull pk2(float a, float b) {
    ull r; asm("mov.b64 %0,{%1,%2};" : "=l"(r) : "f"(a), "f"(b)); return r;
}
__device__ __forceinline__ ull f2fma(ull a, ull b, ull c) {
    ull d; asm("fma.rn.f32x2 %0,%1,%2,%3;" : "=l"(d) : "l"(a), "l"(b), "l"(c)); return d;
}
__device__ __forceinline__ void up2(ull v, float& lo, float& hi) {
    asm("mov.b64 {%0,%1},%2;" : "=f"(lo), "=f"(hi) : "l"(v));
}
__device__ __forceinline__ void cpasync16(uint32_t saddr, const float* g) {
    asm volatile("cp.async.ca.shared.global [%0], [%1], 16;" :: "r"(saddr), "l"(g));
}

// ---------------- prep: block0 = CSR sort; blocks 1.. = weight transposes ----------------
__global__ __launch_bounds__(256) void prep_kernel(
    const int* __restrict__ ei, const float* __restrict__ ew,
    const float* __restrict__ Wq, const float* __restrict__ Wk,
    const float* __restrict__ Wv, const float* __restrict__ Wsk,
    const float* __restrict__ W1, const float* __restrict__ W2) {
    int tid = threadIdx.x;
    if (blockIdx.x == 0) {
        __shared__ int dsts[NEDGE];
        __shared__ int cell[NCELL];
        __shared__ int wsum[8];
        int lane = tid & 31, w = tid >> 5;
        for (int e = tid; e < NEDGE; e += 256) dsts[e] = ei[NEDGE + e];
        for (int c = tid; c < NCELL; c += 256) cell[c] = 0;
        __syncthreads();
        for (int e = tid; e < NEDGE; e += 256)
            atomicAdd(&cell[dsts[e] * NCH + e / CHSZ], 1);
        __syncthreads();
        int base = tid * 8, loc[8], s = 0;
        #pragma unroll
        for (int j = 0; j < 8; j++) {
            int v = (base + j < NCELL) ? cell[base + j] : 0;
            loc[j] = s; s += v;
        }
        int x = s;
        #pragma unroll
        for (int o = 1; o < 32; o <<= 1) {
            int t = __shfl_up_sync(0xffffffffu, x, o);
            if (lane >= o) x += t;
        }
        if (lane == 31) wsum[w] = x;
        int exw = x - s;
        __syncthreads();
        if (tid == 0) {
            int a = 0;
            for (int i = 0; i < 8; i++) { int t = wsum[i]; wsum[i] = a; a += t; }
        }
        __syncthreads();
        int off = wsum[w] + exw;
        #pragma unroll
        for (int j = 0; j < 8; j++) if (base + j < NCELL) cell[base + j] = off + loc[j];
        __syncthreads();
        if (tid < NNODE) g_rowptr[tid] = cell[tid * NCH];
        if (tid == 0) g_rowptr[NNODE] = NEDGE;
        for (int e = tid; e < NEDGE; e += 256) {
            int d = dsts[e];
            int ch = e / CHSZ, b0 = ch * CHSZ;
            int rank = 0;
            for (int e2 = b0; e2 < e; e2++) rank += (dsts[e2] == d);
            int pos = cell[d * NCH + ch] + rank;
            g_srcp[pos] = ei[e]; g_ewp[pos] = ew[e];
        }
    } else {
        int gtid = (blockIdx.x - 1) * 256 + tid, gs = (gridDim.x - 1) * 256;
        for (int t = gtid; t < 32 * 256; t += gs) {
            int k = t >> 8, ch = t & 255;
            float v;
            if (ch < 64)       v = Wq[ch * 32 + k];
            else if (ch < 128) v = Wk[(ch - 64) * 32 + k];
            else if (ch < 192) v = Wv[(ch - 128) * 32 + k];
            else               v = Wsk[(ch - 192) * 32 + k];
            g_W4D[t] = pk2(v, v);
        }
        for (int t = gtid; t < KP1 * HID; t += gs) {
            int k = t >> 8, j = t & 255;
            g_W1U[t] = (k < 97) ? W1[j * 97 + k] : 0.f;
        }
        for (int t = gtid; t < HID * HID; t += gs) {
            int k = t >> 8, j = t & 255;
            g_W2U[t] = W2[j * HID + k];
        }
    }
}

// ---------------- gemm engines ----------------
// barrier-free (small K, weights L1-resident): qkvs (4ch x 8 row-pairs)
template<int K>
__device__ __forceinline__ void gemm_reg(const ull* __restrict__ Wg,
                                         const float* __restrict__ xsrc,
                                         float4 bvv, ull (&acc)[4][8],
                                         int c4, int pbase) {
    #pragma unroll
    for (int rp = 0; rp < 8; rp++) {
        acc[0][rp] = dup2(bvv.x); acc[1][rp] = dup2(bvv.y);
        acc[2][rp] = dup2(bvv.z); acc[3][rp] = dup2(bvv.w);
    }
    const float* xb = xsrc + (size_t)pbase * K * 2;
    const ull* wb = Wg + 4 * c4;
    #pragma unroll 2
    for (int k = 0; k < K; k += 2) {
        ulonglong2 w0a = __ldg((const ulonglong2*)(wb + (size_t)k * 256));
        ulonglong2 w0b = __ldg((const ulonglong2*)(wb + (size_t)k * 256 + 2));
        ulonglong2 w1a = __ldg((const ulonglong2*)(wb + (size_t)(k + 1) * 256));
        ulonglong2 w1b = __ldg((const ulonglong2*)(wb + (size_t)(k + 1) * 256 + 2));
        #pragma unroll
        for (int rp = 0; rp < 8; rp++) {
            ulonglong2 xv = *(const ulonglong2*)(xb + ((size_t)rp * K + k) * 2);
            acc[0][rp] = f2fma(xv.x, w0a.x, acc[0][rp]);
            acc[1][rp] = f2fma(xv.x, w0a.y, acc[1][rp]);
            acc[2][rp] = f2fma(xv.x, w0b.x, acc[2][rp]);
            acc[3][rp] = f2fma(xv.x, w0b.y, acc[3][rp]);
            acc[0][rp] = f2fma(xv.y, w1a.x, acc[0][rp]);
            acc[1][rp] = f2fma(xv.y, w1a.y, acc[1][rp]);
            acc[2][rp] = f2fma(xv.y, w1b.x, acc[2][rp]);
            acc[3][rp] = f2fma(xv.y, w1b.y, acc[3][rp]);
        }
    }
}

// quad-buffered smem k-panels, ONE syncthreads per panel, 2ch x 8 row-pairs (mlp)
// NOTE: caller must __syncthreads() after return before reusing smem aliased with xsrc.
template<int K>
__device__ __forceinline__ void gemm_panels4c2(const float* __restrict__ Wg,
                                               const float* __restrict__ xsrc,
                                               float* __restrict__ wp, uint32_t wp_s32,
                                               float2 bvv, ull (&acc)[2][8],
                                               int c2, int pbase, int tid) {
    const int NP = K / 8;
    #pragma unroll
    for (int p = 0; p < 3; p++) {
        uint32_t dst = wp_s32 + p * 8192;
        cpasync16(dst + tid * 16, Wg + p * 2048 + tid * 4);
        cpasync16(dst + 4096 + tid * 16, Wg + p * 2048 + 1024 + tid * 4);
        asm volatile("cp.async.commit_group;");
    }
    #pragma unroll
    for (int rp = 0; rp < 8; rp++) { acc[0][rp] = dup2(bvv.x); acc[1][rp] = dup2(bvv.y); }
    const float* xb = xsrc + (size_t)pbase * K * 2;
    #pragma unroll 1
    for (int p = 0; p < NP; p++) {
        asm volatile("cp.async.wait_group 2;");
        __syncthreads();
        if (p + 3 < NP) {
            uint32_t dst = wp_s32 + ((p + 3) & 3) * 8192;
            cpasync16(dst + tid * 16, Wg + (p + 3) * 2048 + tid * 4);
            cpasync16(dst + 4096 + tid * 16, Wg + (p + 3) * 2048 + 1024 + tid * 4);
        }
        asm volatile("cp.async.commit_group;");
        const float* wb = wp + (p & 3) * 2048;
        #pragma unroll
        for (int kk2 = 0; kk2 < 4; kk2++) {
            int kl = kk2 * 2;
            float2 wa = *(const float2*)(wb + kl * 256 + 2 * c2);
            float2 wc = *(const float2*)(wb + (kl + 1) * 256 + 2 * c2);
            ull a0 = dup2(wa.x), a1 = dup2(wa.y);
            ull c0 = dup2(wc.x), c1 = dup2(wc.y);
            int kg = p * 8 + kl;
            #pragma unroll
            for (int rp = 0; rp < 8; rp++) {
                ulonglong2 xv = *(const ulonglong2*)(xb + ((size_t)rp * K + kg) * 2);
                acc[0][rp] = f2fma(xv.x, a0, acc[0][rp]);
                acc[1][rp] = f2fma(xv.x, a1, acc[1][rp]);
                acc[0][rp] = f2fma(xv.y, c0, acc[0][rp]);
                acc[1][rp] = f2fma(xv.y, c1, acc[1][rp]);
            }
        }
    }
}

// ---------------- qkvs: batched GEMM, register->global coalesced epilogue ----------------
__global__ __launch_bounds__(256, 2) void qkvs_kernel(
    const float* __restrict__ state, const float* __restrict__ pos,
    const float* __restrict__ bq, const float* __restrict__ bk,
    const float* __restrict__ bv, const float* __restrict__ bsk) {
    __shared__ float xs[2048];     // 32 pr x 32 k x 2
    __shared__ float bias[256];
    int tid = threadIdx.x;
    int c4 = tid & 63, pbase = (tid >> 6) * 8;
    size_t row0 = (size_t)blockIdx.x * MROWS;

    for (int idx = tid; idx < MROWS * 32; idx += 256) {
        int r = idx >> 5, k = idx & 31;
        size_t g = row0 + r;
        int node = (int)(g % NNODE);
        float v = (k < 26) ? state[g * 26 + k] : pos[node * 6 + (k - 26)];
        xs[((r >> 1) * 32 + k) * 2 + (r & 1)] = v;
    }
    {
        int ch = tid;
        float v = (ch < 64) ? bq[ch] : (ch < 128) ? bk[ch - 64]
                : (ch < 192) ? bv[ch - 128] : bsk[ch - 192];
        bias[ch] = v;
    }
    __syncthreads();

    ull acc[4][8];
    gemm_reg<32>(g_W4D, xs, ((const float4*)bias)[c4], acc, c4, pbase);

    int sect = c4 >> 4;
    int ch4 = (c4 & 15) * 4;
    #pragma unroll
    for (int rp = 0; rp < 8; rp++) {
        float l0, h0, l1, h1, l2, h2, l3, h3;
        up2(acc[0][rp], l0, h0); up2(acc[1][rp], l1, h1);
        up2(acc[2][rp], l2, h2); up2(acc[3][rp], l3, h3);
        float4 ev = make_float4(l0, l1, l2, l3);
        float4 ov = make_float4(h0, h1, h2, h3);
        size_t g0 = row0 + 2 * (pbase + rp), g1 = g0 + 1;
        if (sect == 0) {
            *(float4*)(g_q + g0 * 64 + ch4) = ev;
            *(float4*)(g_q + g1 * 64 + ch4) = ov;
        } else if (sect == 1) {
            *(float4*)(g_k + g0 * 64 + ch4) = ev;
            *(float4*)(g_k + g1 * 64 + ch4) = ov;
        } else if (sect == 2) {
            *(float4*)(g_v + g0 * 64 + ch4) = ev;
            *(float4*)(g_v + g1 * 64 + ch4) = ov;
        } else {
            *(float4*)(g_hin + g0 * KP1 + ch4) = ev;
            *(float4*)(g_hin + g1 * KP1 + ch4) = ov;
        }
    }
}

// ---------------- edge: per-batch attention, 512 threads (verified 48 us) ----------------
#define EDGE_SMEM_FLOATS (3*5372 + 3000 + 80 + 64 + 4 + 80 + 80 + 1500)
#define EDGE_SMEM_BYTES  (EDGE_SMEM_FLOATS * 4)

__global__ __launch_bounds__(512, 2) void edge_kernel(
    const float* __restrict__ state, const float* __restrict__ pos,
    const float* __restrict__ We) {
    extern __shared__ float sm[];
    float* qs  = sm;               // 79 x 68
    float* ks  = qs + 5372;
    float* vs  = ks + 5372;
    float* alp = vs + 5372;        // 3000
    float* qWe = alp + 3000;       // 80
    float* wes = qWe + 80;         // 64
    float* tot = wes + 64;         // 4
    int*   rps = (int*)(tot + 4);  // 80
    float* sx  = (float*)(rps + 80);      // 80
    short* srcp_s = (short*)(sx + 80);    // 3000 int16

    int b = blockIdx.x, tid = threadIdx.x, lane = tid & 31, w = tid >> 5;
    size_t base = (size_t)b * NNODE;

    for (int idx = tid; idx < NNODE * 16; idx += 512) {
        int row = idx >> 4, f4 = idx & 15;
        float4 qv = __ldg(((const float4*)(g_q + (base + row) * 64)) + f4);
        float4 kv = __ldg(((const float4*)(g_k + (base + row) * 64)) + f4);
        float4 vv = __ldg(((const float4*)(g_v + (base + row) * 64)) + f4);
        *(float4*)(qs + row * 68 + f4 * 4) = qv;
        *(float4*)(ks + row * 68 + f4 * 4) = kv;
        *(float4*)(vs + row * 68 + f4 * 4) = vv;
    }
    for (int e = tid; e < NEDGE; e += 512) srcp_s[e] = (short)g_srcp[e];
    if (tid <= NNODE) rps[tid] = g_rowptr[tid];
    if (tid >= 128 && tid < 192) wes[tid - 128] = We[tid - 128];
    if (tid >= 256 && tid < 256 + NNODE) sx[tid - 256] = __ldg(state + (base + tid - 256) * 26 + 1);
    __syncthreads();

    if (w == 0) {
        float s = 0.f;
        for (int j = lane; j < NNODE; j += 32) s += sx[j];
        s = wredsum(s);
        if (lane == 0) tot[0] = s;
    }
    if (tid < NNODE) {
        float a = 0.f;
        const float* qr = qs + tid * 68;
        #pragma unroll 8
        for (int d = 0; d < 64; d++) a += qr[d] * wes[d];
        qWe[tid] = a;
    }
    __syncthreads();

    {
        int g = lane >> 3, li = lane & 7;
        for (int i = w; i < NNODE; i += 16) {
            int s0 = rps[i], e1 = rps[i + 1];
            const float4* qr = (const float4*)(qs + i * 68 + li * 8);
            float4 q0 = qr[0], q1 = qr[1];
            float qwei = qWe[i];
            #pragma unroll 1
            for (int eb = s0; eb < e1; eb += 4) {
                int e = eb + g;
                bool valid = e < e1;
                int ec = valid ? e : e1 - 1;
                int ss = srcp_s[ec];
                float ewv = __ldg(g_ewp + ec);
                const float4* kr = (const float4*)(ks + ss * 68 + li * 8);
                float4 k0 = kr[0], k1 = kr[1];
                float p = q0.x*k0.x + q0.y*k0.y + q0.z*k0.z + q0.w*k0.w
                        + q1.x*k1.x + q1.y*k1.y + q1.z*k1.z + q1.w*k1.w;
                p += __shfl_xor_sync(0xffffffffu, p, 1);
                p += __shfl_xor_sync(0xffffffffu, p, 2);
                p += __shfl_xor_sync(0xffffffffu, p, 4);
                if (li == 0 && valid) alp[e] = 0.125f * (p + ewv * qwei);
            }
        }
    }
    for (int idx = tid; idx < NNODE * 40; idx += 512) {
        int i = idx / 40, c = idx - i * 40;
        float v;
        if (c == 0) v = tot[0];
        else if (c <= 26) v = __ldg(state + (base + i) * 26 + (c - 1));
        else if (c <= 32) v = __ldg(pos + i * 6 + (c - 27));
        else v = 0.f;
        g_hin[(base + i) * KP1 + 64 + c] = v;
    }
    __syncthreads();

    float we0 = wes[lane], we1 = wes[lane + 32];
    for (int i = w; i < NNODE; i += 16) {
        int s0 = rps[i], e1 = rps[i + 1];
        float a0 = 0.f, a1 = 0.f;
        if (e1 > s0) {
            float m = -1e30f;
            for (int e = s0 + lane; e < e1; e += 32) m = fmaxf(m, alp[e]);
            m = wredmax(m);
            float den = 0.f, sew = 0.f;
            for (int e = s0 + lane; e < e1; e += 32) {
                float ex = __expf(alp[e] - m);
                alp[e] = ex; den += ex; sew += ex * __ldg(g_ewp + e);
            }
            den = wredsum(den); sew = wredsum(sew);
            float inv = 1.f / (den + 1e-16f);
            float b0 = 0.f, b1 = 0.f;
            int e = s0;
            #pragma unroll 1
            for (; e + 1 < e1; e += 2) {
                float w0 = alp[e], w1v = alp[e + 1];
                int sA = srcp_s[e], sB = srcp_s[e + 1];
                a0 += w0 * vs[sA * 68 + lane];
                a1 += w0 * vs[sA * 68 + lane + 32];
                b0 += w1v * vs[sB * 68 + lane];
                b1 += w1v * vs[sB * 68 + lane + 32];
            }
            if (e < e1) {
                float w0 = alp[e]; int sA = srcp_s[e];
                a0 += w0 * vs[sA * 68 + lane];
                a1 += w0 * vs[sA * 68 + lane + 32];
            }
            a0 = (a0 + b0 + sew * we0) * inv;
            a1 = (a1 + b1 + sew * we1) * inv;
        }
        size_t r = base + i;
        float s0v = g_hin[r * KP1 + lane];
        float s1v = g_hin[r * KP1 + lane + 32];
        g_hin[r * KP1 + lane]      = fmaxf(a0 + s0v, 0.f);
        g_hin[r * KP1 + lane + 32] = fmaxf(a1 + s1v, 0.f);
    }
}

// ---------------- MLP: 32 rows/CTA, 3 CTAs/SM, 2ch x 8 row-pairs per thread ----------------
// smem floats: wp 8192 | buf 8192 (xs alias + hb) | mu 32 | rsd 32 | w3 256 = 16704 (66.8 KB)
#define MLP_SMEM_FLOATS (8192 + 8192 + 32 + 32 + 256)
#define MLP_SMEM_BYTES  (MLP_SMEM_FLOATS * 4)

__global__ __launch_bounds__(256, 3) void mlp_kernel(
    const float* __restrict__ b1, const float* __restrict__ g1, const float* __restrict__ be1,
    const float* __restrict__ b2, const float* __restrict__ g2, const float* __restrict__ be2,
    const float* __restrict__ W3, const float* __restrict__ b3) {
    extern __shared__ float sm[];
    float* wp  = sm;                  // 4 x 8 x 256 weight panels
    float* buf = sm + 8192;           // xs (first 3328) aliased with hb (8192)
    float* xs  = buf;
    float* hb  = buf;
    float* mu  = buf + 8192;          // 32
    float* rsd = mu + 32;             // 32
    float* w3s = rsd + 32;            // 256
    ull* hbp = (ull*)hb;
    uint32_t wp_s32 = (uint32_t)__cvta_generic_to_shared(wp);
    int tid = threadIdx.x, lane = tid & 31, w = tid >> 5;
    int c2 = tid & 127, pbase = (tid >> 7) * 8;   // 2 ch/thread, 2 groups x 8 row-pairs
    size_t row0 = (size_t)blockIdx.x * MLPR;

    {
        const float4* src4 = (const float4*)(g_hin + row0 * KP1);
        for (int i = tid; i < MLPR * 26; i += 256) {
            int r = i / 26, q = i - r * 26;
            float4 f = src4[i];
            float* d = xs + ((r >> 1) * KP1 + 4 * q) * 2 + (r & 1);
            d[0] = f.x; d[2] = f.y; d[4] = f.z; d[6] = f.w;
        }
    }
    w3s[tid] = W3[tid];
    __syncthreads();

    ull acc[2][8];
    // ---- layer 1 ----
    gemm_panels4c2<KP1>(g_W1U, xs, wp, wp_s32, ((const float2*)b1)[c2], acc, c2, pbase, tid);
    __syncthreads();   // xs reads done before hb (alias) writes
    #pragma unroll
    for (int rp = 0; rp < 8; rp++)
        *(ulonglong2*)(hbp + (size_t)(pbase + rp) * HID + 2 * c2) =
            make_ulonglong2(acc[0][rp], acc[1][rp]);
    __syncthreads();
    for (int r = w; r < MLPR; r += 8) {
        int pr = r >> 1, par = r & 1;
        float s = 0.f, s2 = 0.f;
        #pragma unroll
        for (int t = 0; t < 8; t++) {
            float v = hb[((size_t)pr * HID + lane + t * 32) * 2 + par];
            s += v; s2 += v * v;
        }
        s = wredsum(s); s2 = wredsum(s2);
        if (lane == 0) {
            float m = s * (1.f / HID);
            mu[r] = m;
            rsd[r] = rsqrtf(s2 * (1.f / HID) - m * m + 1e-5f);
        }
    }
    __syncthreads();
    {
        float2 gv = ((const float2*)g1)[c2], bev = ((const float2*)be1)[c2];
        float ga[2] = {gv.x, gv.y}, ba[2] = {bev.x, bev.y};
        #pragma unroll
        for (int rp = 0; rp < 8; rp++) {
            int pr = pbase + rp;
            float m0 = mu[2*pr], m1 = mu[2*pr+1], r0 = rsd[2*pr], r1 = rsd[2*pr+1];
            ull o[2];
            #pragma unroll
            for (int c = 0; c < 2; c++) {
                float lo, hi; up2(acc[c][rp], lo, hi);
                float h0 = (lo - m0) * r0 * ga[c] + ba[c];
                float h1 = (hi - m1) * r1 * ga[c] + ba[c];
                h0 = h0 > 0.f ? h0 : 0.01f * h0;
                h1 = h1 > 0.f ? h1 : 0.01f * h1;
                o[c] = pk2(h0, h1);
            }
            *(ulonglong2*)(hbp + (size_t)pr * HID + 2 * c2) = make_ulonglong2(o[0], o[1]);
        }
    }
    __syncthreads();

    // ---- layer 2 ----
    gemm_panels4c2<HID>(g_W2U, hb, wp, wp_s32, ((const float2*)b2)[c2], acc, c2, pbase, tid);
    __syncthreads();   // hb reads done before overwrite
    #pragma unroll
    for (int rp = 0; rp < 8; rp++)
        *(ulonglong2*)(hbp + (size_t)(pbase + rp) * HID + 2 * c2) =
            make_ulonglong2(acc[0][rp], acc[1][rp]);
    __syncthreads();
    for (int r = w; r < MLPR; r += 8) {
        int pr = r >> 1, par = r & 1;
        float s = 0.f, s2 = 0.f;
        #pragma unroll
        for (int t = 0; t < 8; t++) {
            float v = hb[((size_t)pr * HID + lane + t * 32) * 2 + par];
            s += v; s2 += v * v;
        }
        s = wredsum(s); s2 = wredsum(s2);
        if (lane == 0) {
            float m = s * (1.f / HID);
            mu[r] = m;
            rsd[r] = rsqrtf(s2 * (1.f / HID) - m * m + 1e-5f);
        }
    }
    __syncthreads();
    {
        float2 gv = ((const float2*)g2)[c2], bev = ((const float2*)be2)[c2];
        float ga[2] = {gv.x, gv.y}, ba[2] = {bev.x, bev.y};
        #pragma unroll
        for (int rp = 0; rp < 8; rp++) {
            int pr = pbase + rp;
            float m0 = mu[2*pr], m1 = mu[2*pr+1], r0 = rsd[2*pr], r1 = rsd[2*pr+1];
            ull o[2];
            #pragma unroll
            for (int c = 0; c < 2; c++) {
                float lo, hi; up2(acc[c][rp], lo, hi);
                float w3c = w3s[2 * c2 + c];
                float h0 = (lo - m0) * r0 * ga[c] + ba[c];
                float h1 = (hi - m1) * r1 * ga[c] + ba[c];
                h0 = h0 > 0.f ? h0 : 0.01f * h0;
                h1 = h1 > 0.f ? h1 : 0.01f * h1;
                o[c] = pk2(h0 * w3c, h1 * w3c);
            }
            *(ulonglong2*)(hbp + (size_t)pr * HID + 2 * c2) = make_ulonglong2(o[0], o[1]);
        }
    }
    __syncthreads();
    float b3v = b3[0];
    for (int r = w; r < MLPR; r += 8) {
        int pr = r >> 1, par = r & 1;
        float s = 0.f;
        #pragma unroll
        for (int t = 0; t < 8; t++)
            s += hb[((size_t)pr * HID + lane + t * 32) * 2 + par];
        s = wredsum(s);
        if (lane == 0) {
            float yv = s + b3v;
            g_conc[row0 + r] = (yv > 20.f) ? yv : log1pf(expf(yv));
        }
    }
}

// ---------------- final normalize per batch ----------------
__global__ __launch_bounds__(128) void final_kernel(float* __restrict__ out) {
    __shared__ float sb[4];
    int b = blockIdx.x, tid = threadIdx.x, lane = tid & 31, w = tid >> 5;
    float v = (tid < NNODE) ? g_conc[b * NNODE + tid] : 0.f;
    float s = v;
    #pragma unroll
    for (int o = 16; o; o >>= 1) s += __shfl_xor_sync(0xffffffffu, s, o);
    if (lane == 0) sb[w] = s;
    __syncthreads();
    float tt = sb[0] + sb[1] + sb[2] + sb[3];
    if (tid < NNODE) out[b * NNODE + tid] = v / (tt + 1e-20f);
}

// ---------------- launch ----------------
extern "C" void kernel_launch(void* const* d_in, const int* in_sizes, int n_in,
                              void* d_out, int out_size) {
    const float* state = (const float*)d_in[0];
    const float* pos   = (const float*)d_in[1];
    const float* ew    = (const float*)d_in[2];
    const float* Wq  = (const float*)d_in[3];  const float* bq  = (const float*)d_in[4];
    const float* Wk  = (const float*)d_in[5];  const float* bk  = (const float*)d_in[6];
    const float* Wv  = (const float*)d_in[7];  const float* bv  = (const float*)d_in[8];
    const float* We  = (const float*)d_in[9];
    const float* Wsk = (const float*)d_in[10]; const float* bsk = (const float*)d_in[11];
    const float* W1  = (const float*)d_in[12]; const float* b1  = (const float*)d_in[13];
    const float* g1  = (const float*)d_in[14]; const float* be1 = (const float*)d_in[15];
    const float* W2  = (const float*)d_in[16]; const float* b2  = (const float*)d_in[17];
    const float* g2  = (const float*)d_in[18]; const float* be2 = (const float*)d_in[19];
    const float* W3  = (const float*)d_in[20]; const float* b3  = (const float*)d_in[21];
    const int*   ei  = (const int*)d_in[22];
    float* out = (float*)d_out;

    cudaFuncSetAttribute(edge_kernel, cudaFuncAttributeMaxDynamicSharedMemorySize, EDGE_SMEM_BYTES);
    cudaFuncSetAttribute(mlp_kernel,  cudaFuncAttributeMaxDynamicSharedMemorySize, MLP_SMEM_BYTES);

    prep_kernel<<<180, 256>>>(ei, ew, Wq, Wk, Wv, Wsk, W1, W2);        // 1
    qkvs_kernel<<<NROWS / MROWS, 256>>>(state, pos, bq, bk, bv, bsk);  // 2
    edge_kernel<<<BATCH, 512, EDGE_SMEM_BYTES>>>(state, pos, We);      // 3
    mlp_kernel<<<NROWS / MLPR, 256, MLP_SMEM_BYTES>>>(b1, g1, be1, b2, g2, be2, W3, b3); // 4 (profiled)
    final_kernel<<<BATCH, 128>>>(out);                                 // 5
}

// round 16
// speedup vs baseline: 1.0215x; 1.0215x over previous
#include <cuda_runtime.h>
#include <cstdint>

typedef unsigned long long ull;

#define BATCH 256
#define NNODE 79
#define HID 256
#define NEDGE 3000
#define KP1 104
#define NROWS (BATCH*NNODE)     // 20224
#define MROWS 64                // qkvs rows/CTA
#define MLPR 32                 // mlp rows/CTA
#define ETHR 768                // edge threads/CTA (24 warps)
#define NCH 24
#define CHSZ 125
#define NCELL (NNODE*NCH)

// ---------------- device scratch ----------------
__device__ int   g_srcp[NEDGE];
__device__ float g_ewp[NEDGE];
__device__ int   g_rowptr[NNODE + 1];
__device__ ull   g_W4D[32 * 256];        // k-major stacked q|k|v|skip, f32x2-dup (qkvs)
__device__ float g_W1U[KP1 * HID];       // k-major (mlp panels)
__device__ float g_W2U[HID * HID];
__device__ float g_q[(size_t)NROWS * 64];
__device__ float g_k[(size_t)NROWS * 64];
__device__ float g_v[(size_t)NROWS * 64];
__device__ float g_hin[(size_t)NROWS * KP1];
__device__ float g_conc[NROWS];

__device__ __forceinline__ float wredsum(float v) {
    #pragma unroll
    for (int o = 16; o; o >>= 1) v += __shfl_xor_sync(0xffffffffu, v, o);
    return v;
}
__device__ __forceinline__ float wredmax(float v) {
    #pragma unroll
    for (int o = 16; o; o >>= 1) v = fmaxf(v, __shfl_xor_sync(0xffffffffu, v, o));
    return v;
}
__device__ __forceinline__ ull dup2(float v) {
    ull r; asm("mov.b64 %0,{%1,%1};" : "=l"(r) : "f"(v)); return r;
}
__device__ __forceinline__ ull pk2(float a, float b) {
    ull r; asm("mov.b64 %0,{%1,%2};" : "=l"(r) : "f"(a), "f"(b)); return r;
}
__device__ __forceinline__ ull f2fma(ull a, ull b, ull c) {
    ull d; asm("fma.rn.f32x2 %0,%1,%2,%3;" : "=l"(d) : "l"(a), "l"(b), "l"(c)); return d;
}
__device__ __forceinline__ void up2(ull v, float& lo, float& hi) {
    asm("mov.b64 {%0,%1},%2;" : "=f"(lo), "=f"(hi) : "l"(v));
}
__device__ __forceinline__ void cpasync16(uint32_t saddr, const float* g) {
    asm volatile("cp.async.ca.shared.global [%0], [%1], 16;" :: "r"(saddr), "l"(g));
}

// ---------------- prep 1/2: CSR sort ----------------
__global__ __launch_bounds__(256) void prep_sort(const int* __restrict__ ei,
                                                 const float* __restrict__ ew) {
    __shared__ int dsts[NEDGE];
    __shared__ int cell[NCELL];
    __shared__ int wsum[8];
    int tid = threadIdx.x, lane = tid & 31, w = tid >> 5;
    for (int e = tid; e < NEDGE; e += 256) dsts[e] = ei[NEDGE + e];
    for (int c = tid; c < NCELL; c += 256) cell[c] = 0;
    __syncthreads();
    for (int e = tid; e < NEDGE; e += 256)
        atomicAdd(&cell[dsts[e] * NCH + e / CHSZ], 1);
    __syncthreads();
    int base = tid * 8, loc[8], s = 0;
    #pragma unroll
    for (int j = 0; j < 8; j++) {
        int v = (base + j < NCELL) ? cell[base + j] : 0;
        loc[j] = s; s += v;
    }
    int x = s;
    #pragma unroll
    for (int o = 1; o < 32; o <<= 1) {
        int t = __shfl_up_sync(0xffffffffu, x, o);
        if (lane >= o) x += t;
    }
    if (lane == 31) wsum[w] = x;
    int exw = x - s;
    __syncthreads();
    if (tid == 0) {
        int a = 0;
        for (int i = 0; i < 8; i++) { int t = wsum[i]; wsum[i] = a; a += t; }
    }
    __syncthreads();
    int off = wsum[w] + exw;
    #pragma unroll
    for (int j = 0; j < 8; j++) if (base + j < NCELL) cell[base + j] = off + loc[j];
    __syncthreads();
    if (tid < NNODE) g_rowptr[tid] = cell[tid * NCH];
    if (tid == 0) g_rowptr[NNODE] = NEDGE;
    for (int e = tid; e < NEDGE; e += 256) {
        int d = dsts[e];
        int ch = e / CHSZ, b0 = ch * CHSZ;
        int rank = 0;
        for (int e2 = b0; e2 < e; e2++) rank += (dsts[e2] == d);
        int pos = cell[d * NCH + ch] + rank;
        g_srcp[pos] = ei[e]; g_ewp[pos] = ew[e];
    }
}

// ---------------- prep 2/2: weight transposes ----------------
__global__ __launch_bounds__(256) void prep_weights(
    const float* __restrict__ Wq, const float* __restrict__ Wk,
    const float* __restrict__ Wv, const float* __restrict__ Wsk,
    const float* __restrict__ W1, const float* __restrict__ W2) {
    int gtid = blockIdx.x * 256 + threadIdx.x, gs = gridDim.x * 256;
    for (int t = gtid; t < 32 * 256; t += gs) {
        int k = t >> 8, ch = t & 255;
        float v;
        if (ch < 64)       v = Wq[ch * 32 + k];
        else if (ch < 128) v = Wk[(ch - 64) * 32 + k];
        else if (ch < 192) v = Wv[(ch - 128) * 32 + k];
        else               v = Wsk[(ch - 192) * 32 + k];
        g_W4D[t] = pk2(v, v);
    }
    for (int t = gtid; t < KP1 * HID; t += gs) {
        int k = t >> 8, j = t & 255;
        g_W1U[t] = (k < 97) ? W1[j * 97 + k] : 0.f;
    }
    for (int t = gtid; t < HID * HID; t += gs) {
        int k = t >> 8, j = t & 255;
        g_W2U[t] = W2[j * HID + k];
    }
}

// ---------------- gemm engines ----------------
// barrier-free (small K, weights L1-resident): qkvs (4ch x 8 row-pairs)
template<int K>
__device__ __forceinline__ void gemm_reg(const ull* __restrict__ Wg,
                                         const float* __restrict__ xsrc,
                                         float4 bvv, ull (&acc)[4][8],
                                         int c4, int pbase) {
    #pragma unroll
    for (int rp = 0; rp < 8; rp++) {
        acc[0][rp] = dup2(bvv.x); acc[1][rp] = dup2(bvv.y);
        acc[2][rp] = dup2(bvv.z); acc[3][rp] = dup2(bvv.w);
    }
    const float* xb = xsrc + (size_t)pbase * K * 2;
    const ull* wb = Wg + 4 * c4;
    #pragma unroll 2
    for (int k = 0; k < K; k += 2) {
        ulonglong2 w0a = __ldg((const ulonglong2*)(wb + (size_t)k * 256));
        ulonglong2 w0b = __ldg((const ulonglong2*)(wb + (size_t)k * 256 + 2));
        ulonglong2 w1a = __ldg((const ulonglong2*)(wb + (size_t)(k + 1) * 256));
        ulonglong2 w1b = __ldg((const ulonglong2*)(wb + (size_t)(k + 1) * 256 + 2));
        #pragma unroll
        for (int rp = 0; rp < 8; rp++) {
            ulonglong2 xv = *(const ulonglong2*)(xb + ((size_t)rp * K + k) * 2);
            acc[0][rp] = f2fma(xv.x, w0a.x, acc[0][rp]);
            acc[1][rp] = f2fma(xv.x, w0a.y, acc[1][rp]);
            acc[2][rp] = f2fma(xv.x, w0b.x, acc[2][rp]);
            acc[3][rp] = f2fma(xv.x, w0b.y, acc[3][rp]);
            acc[0][rp] = f2fma(xv.y, w1a.x, acc[0][rp]);
            acc[1][rp] = f2fma(xv.y, w1a.y, acc[1][rp]);
            acc[2][rp] = f2fma(xv.y, w1b.x, acc[2][rp]);
            acc[3][rp] = f2fma(xv.y, w1b.y, acc[3][rp]);
        }
    }
}

// quad-buffered smem k-panels, ONE syncthreads per panel, 4ch x 4 row-pairs (R13 mlp)
// NOTE: caller must __syncthreads() after return before reusing smem aliased with xsrc.
template<int K>
__device__ __forceinline__ void gemm_panels4(const float* __restrict__ Wg,
                                             const float* __restrict__ xsrc,
                                             float* __restrict__ wp, uint32_t wp_s32,
                                             float4 bvv, ull (&acc)[4][4],
                                             int c4, int pbase, int tid) {
    const int NP = K / 8;
    #pragma unroll
    for (int p = 0; p < 3; p++) {
        uint32_t dst = wp_s32 + p * 8192;
        cpasync16(dst + tid * 16, Wg + p * 2048 + tid * 4);
        cpasync16(dst + 4096 + tid * 16, Wg + p * 2048 + 1024 + tid * 4);
        asm volatile("cp.async.commit_group;");
    }
    #pragma unroll
    for (int rp = 0; rp < 4; rp++) {
        acc[0][rp] = dup2(bvv.x); acc[1][rp] = dup2(bvv.y);
        acc[2][rp] = dup2(bvv.z); acc[3][rp] = dup2(bvv.w);
    }
    const float* xb = xsrc + (size_t)pbase * K * 2;
    #pragma unroll 1
    for (int p = 0; p < NP; p++) {
        asm volatile("cp.async.wait_group 2;");
        __syncthreads();
        if (p + 3 < NP) {
            uint32_t dst = wp_s32 + ((p + 3) & 3) * 8192;
            cpasync16(dst + tid * 16, Wg + (p + 3) * 2048 + tid * 4);
            cpasync16(dst + 4096 + tid * 16, Wg + (p + 3) * 2048 + 1024 + tid * 4);
        }
        asm volatile("cp.async.commit_group;");
        const float* wb = wp + (p & 3) * 2048;
        #pragma unroll
        for (int kk2 = 0; kk2 < 4; kk2++) {
            int kl = kk2 * 2;
            float4 wa = *(const float4*)(wb + kl * 256 + 4 * c4);
            float4 wc = *(const float4*)(wb + (kl + 1) * 256 + 4 * c4);
            ull a0 = dup2(wa.x), a1 = dup2(wa.y), a2 = dup2(wa.z), a3 = dup2(wa.w);
            ull c0 = dup2(wc.x), c1 = dup2(wc.y), c2 = dup2(wc.z), c3 = dup2(wc.w);
            int kg = p * 8 + kl;
            #pragma unroll
            for (int rp = 0; rp < 4; rp++) {
                ulonglong2 xv = *(const ulonglong2*)(xb + ((size_t)rp * K + kg) * 2);
                acc[0][rp] = f2fma(xv.x, a0, acc[0][rp]);
                acc[1][rp] = f2fma(xv.x, a1, acc[1][rp]);
                acc[2][rp] = f2fma(xv.x, a2, acc[2][rp]);
                acc[3][rp] = f2fma(xv.x, a3, acc[3][rp]);
                acc[0][rp] = f2fma(xv.y, c0, acc[0][rp]);
                acc[1][rp] = f2fma(xv.y, c1, acc[1][rp]);
                acc[2][rp] = f2fma(xv.y, c2, acc[2][rp]);
                acc[3][rp] = f2fma(xv.y, c3, acc[3][rp]);
            }
        }
    }
}

// ---------------- qkvs: batched GEMM, register->global coalesced epilogue ----------------
__global__ __launch_bounds__(256, 2) void qkvs_kernel(
    const float* __restrict__ state, const float* __restrict__ pos,
    const float* __restrict__ bq, const float* __restrict__ bk,
    const float* __restrict__ bv, const float* __restrict__ bsk) {
    __shared__ float xs[2048];     // 32 pr x 32 k x 2
    __shared__ float bias[256];
    int tid = threadIdx.x;
    int c4 = tid & 63, pbase = (tid >> 6) * 8;
    size_t row0 = (size_t)blockIdx.x * MROWS;

    for (int idx = tid; idx < MROWS * 32; idx += 256) {
        int r = idx >> 5, k = idx & 31;
        size_t g = row0 + r;
        int node = (int)(g % NNODE);
        float v = (k < 26) ? state[g * 26 + k] : pos[node * 6 + (k - 26)];
        xs[((r >> 1) * 32 + k) * 2 + (r & 1)] = v;
    }
    {
        int ch = tid;
        float v = (ch < 64) ? bq[ch] : (ch < 128) ? bk[ch - 64]
                : (ch < 192) ? bv[ch - 128] : bsk[ch - 192];
        bias[ch] = v;
    }
    __syncthreads();

    ull acc[4][8];
    gemm_reg<32>(g_W4D, xs, ((const float4*)bias)[c4], acc, c4, pbase);

    int sect = c4 >> 4;
    int ch4 = (c4 & 15) * 4;
    #pragma unroll
    for (int rp = 0; rp < 8; rp++) {
        float l0, h0, l1, h1, l2, h2, l3, h3;
        up2(acc[0][rp], l0, h0); up2(acc[1][rp], l1, h1);
        up2(acc[2][rp], l2, h2); up2(acc[3][rp], l3, h3);
        float4 ev = make_float4(l0, l1, l2, l3);
        float4 ov = make_float4(h0, h1, h2, h3);
        size_t g0 = row0 + 2 * (pbase + rp), g1 = g0 + 1;
        if (sect == 0) {
            *(float4*)(g_q + g0 * 64 + ch4) = ev;
            *(float4*)(g_q + g1 * 64 + ch4) = ov;
        } else if (sect == 1) {
            *(float4*)(g_k + g0 * 64 + ch4) = ev;
            *(float4*)(g_k + g1 * 64 + ch4) = ov;
        } else if (sect == 2) {
            *(float4*)(g_v + g0 * 64 + ch4) = ev;
            *(float4*)(g_v + g1 * 64 + ch4) = ov;
        } else {
            *(float4*)(g_hin + g0 * KP1 + ch4) = ev;
            *(float4*)(g_hin + g1 * KP1 + ch4) = ov;
        }
    }
}

// ---------------- edge: per-batch attention, 768 threads (profiled) ----------------
#define EDGE_SMEM_FLOATS (3*5372 + 3000 + 80 + 64 + 4 + 80 + 80 + 1500)
#define EDGE_SMEM_BYTES  (EDGE_SMEM_FLOATS * 4)

__global__ __launch_bounds__(ETHR) void edge_kernel(
    const float* __restrict__ state, const float* __restrict__ pos,
    const float* __restrict__ We) {
    extern __shared__ float sm[];
    float* qs  = sm;               // 79 x 68
    float* ks  = qs + 5372;
    float* vs  = ks + 5372;
    float* alp = vs + 5372;        // 3000
    float* qWe = alp + 3000;       // 80
    float* wes = qWe + 80;         // 64
    float* tot = wes + 64;         // 4
    int*   rps = (int*)(tot + 4);  // 80
    float* sx  = (float*)(rps + 80);      // 80
    short* srcp_s = (short*)(sx + 80);    // 3000 int16

    int b = blockIdx.x, tid = threadIdx.x, lane = tid & 31, w = tid >> 5;  // 24 warps
    size_t base = (size_t)b * NNODE;

    for (int idx = tid; idx < NNODE * 16; idx += ETHR) {
        int row = idx >> 4, f4 = idx & 15;
        float4 qv = __ldg(((const float4*)(g_q + (base + row) * 64)) + f4);
        float4 kv = __ldg(((const float4*)(g_k + (base + row) * 64)) + f4);
        float4 vv = __ldg(((const float4*)(g_v + (base + row) * 64)) + f4);
        *(float4*)(qs + row * 68 + f4 * 4) = qv;
        *(float4*)(ks + row * 68 + f4 * 4) = kv;
        *(float4*)(vs + row * 68 + f4 * 4) = vv;
    }
    for (int e = tid; e < NEDGE; e += ETHR) srcp_s[e] = (short)g_srcp[e];
    if (tid <= NNODE) rps[tid] = g_rowptr[tid];
    if (tid >= 128 && tid < 192) wes[tid - 128] = We[tid - 128];
    if (tid >= 256 && tid < 256 + NNODE) sx[tid - 256] = __ldg(state + (base + tid - 256) * 26 + 1);
    __syncthreads();

    if (w == 0) {
        float s = 0.f;
        for (int j = lane; j < NNODE; j += 32) s += sx[j];
        s = wredsum(s);
        if (lane == 0) tot[0] = s;
    }
    if (tid < NNODE) {
        float a = 0.f;
        const float* qr = qs + tid * 68;
        #pragma unroll 8
        for (int d = 0; d < 64; d++) a += qr[d] * wes[d];
        qWe[tid] = a;
    }
    __syncthreads();

    {
        int g = lane >> 3, li = lane & 7;
        for (int i = w; i < NNODE; i += 24) {
            int s0 = rps[i], e1 = rps[i + 1];
            const float4* qr = (const float4*)(qs + i * 68 + li * 8);
            float4 q0 = qr[0], q1 = qr[1];
            float qwei = qWe[i];
            #pragma unroll 1
            for (int eb = s0; eb < e1; eb += 4) {
                int e = eb + g;
                bool valid = e < e1;
                int ec = valid ? e : e1 - 1;
                int ss = srcp_s[ec];
                float ewv = __ldg(g_ewp + ec);
                const float4* kr = (const float4*)(ks + ss * 68 + li * 8);
                float4 k0 = kr[0], k1 = kr[1];
                float p = q0.x*k0.x + q0.y*k0.y + q0.z*k0.z + q0.w*k0.w
                        + q1.x*k1.x + q1.y*k1.y + q1.z*k1.z + q1.w*k1.w;
                p += __shfl_xor_sync(0xffffffffu, p, 1);
                p += __shfl_xor_sync(0xffffffffu, p, 2);
                p += __shfl_xor_sync(0xffffffffu, p, 4);
                if (li == 0 && valid) alp[e] = 0.125f * (p + ewv * qwei);
            }
        }
    }
    for (int idx = tid; idx < NNODE * 40; idx += ETHR) {
        int i = idx / 40, c = idx - i * 40;
        float v;
        if (c == 0) v = tot[0];
        else if (c <= 26) v = __ldg(state + (base + i) * 26 + (c - 1));
        else if (c <= 32) v = __ldg(pos + i * 6 + (c - 27));
        else v = 0.f;
        g_hin[(base + i) * KP1 + 64 + c] = v;
    }
    __syncthreads();

    float we0 = wes[lane], we1 = wes[lane + 32];
    for (int i = w; i < NNODE; i += 24) {
        int s0 = rps[i], e1 = rps[i + 1];
        float a0 = 0.f, a1 = 0.f;
        if (e1 > s0) {
            float m = -1e30f;
            for (int e = s0 + lane; e < e1; e += 32) m = fmaxf(m, alp[e]);
            m = wredmax(m);
            float den = 0.f, sew = 0.f;
            for (int e = s0 + lane; e < e1; e += 32) {
                float ex = __expf(alp[e] - m);
                alp[e] = ex; den += ex; sew += ex * __ldg(g_ewp + e);
            }
            den = wredsum(den); sew = wredsum(sew);
            float inv = 1.f / (den + 1e-16f);
            float b0 = 0.f, b1 = 0.f;
            int e = s0;
            #pragma unroll 1
            for (; e + 1 < e1; e += 2) {
                float w0 = alp[e], w1v = alp[e + 1];
                int sA = srcp_s[e], sB = srcp_s[e + 1];
                a0 += w0 * vs[sA * 68 + lane];
                a1 += w0 * vs[sA * 68 + lane + 32];
                b0 += w1v * vs[sB * 68 + lane];
                b1 += w1v * vs[sB * 68 + lane + 32];
            }
            if (e < e1) {
                float w0 = alp[e]; int sA = srcp_s[e];
                a0 += w0 * vs[sA * 68 + lane];
                a1 += w0 * vs[sA * 68 + lane + 32];
            }
            a0 = (a0 + b0 + sew * we0) * inv;
            a1 = (a1 + b1 + sew * we1) * inv;
        }
        size_t r = base + i;
        float s0v = g_hin[r * KP1 + lane];
        float s1v = g_hin[r * KP1 + lane + 32];
        g_hin[r * KP1 + lane]      = fmaxf(a0 + s0v, 0.f);
        g_hin[r * KP1 + lane + 32] = fmaxf(a1 + s1v, 0.f);
    }
}

// ---------------- MLP: R13 exact — 32 rows/CTA, 3 CTAs/SM, 4ch x 4 row-pairs ----------------
// smem floats: wp 8192 | buf 8192 (xs alias + hb) | mu 32 | rsd 32 | w3 256 = 16704 (66.8 KB)
#define MLP_SMEM_FLOATS (8192 + 8192 + 32 + 32 + 256)
#define MLP_SMEM_BYTES  (MLP_SMEM_FLOATS * 4)

__global__ __launch_bounds__(256, 3) void mlp_kernel(
    const float* __restrict__ b1, const float* __restrict__ g1, const float* __restrict__ be1,
    const float* __restrict__ b2, const float* __restrict__ g2, const float* __restrict__ be2,
    const float* __restrict__ W3, const float* __restrict__ b3) {
    extern __shared__ float sm[];
    float* wp  = sm;                  // 4 x 8 x 256 weight panels
    float* buf = sm + 8192;           // xs (first 3328) aliased with hb (8192)
    float* xs  = buf;
    float* hb  = buf;
    float* mu  = buf + 8192;          // 32
    float* rsd = mu + 32;             // 32
    float* w3s = rsd + 32;            // 256
    ull* hbp = (ull*)hb;
    uint32_t wp_s32 = (uint32_t)__cvta_generic_to_shared(wp);
    int tid = threadIdx.x, lane = tid & 31, w = tid >> 5;
    int c4 = tid & 63, pbase = (tid >> 6) * 4;   // 4 row-pairs per group
    size_t row0 = (size_t)blockIdx.x * MLPR;

    {
        const float4* src4 = (const float4*)(g_hin + row0 * KP1);
        for (int i = tid; i < MLPR * 26; i += 256) {
            int r = i / 26, q = i - r * 26;
            float4 f = src4[i];
            float* d = xs + ((r >> 1) * KP1 + 4 * q) * 2 + (r & 1);
            d[0] = f.x; d[2] = f.y; d[4] = f.z; d[6] = f.w;
        }
    }
    w3s[tid] = W3[tid];
    __syncthreads();

    ull acc[4][4];
    // ---- layer 1 ----
    gemm_panels4<KP1>(g_W1U, xs, wp, wp_s32, ((const float4*)b1)[c4], acc, c4, pbase, tid);
    __syncthreads();   // xs reads done before hb (alias) writes
    #pragma unroll
    for (int rp = 0; rp < 4; rp++)
        #pragma unroll
        for (int c = 0; c < 4; c++)
            hbp[(size_t)(pbase + rp) * HID + 4 * c4 + c] = acc[c][rp];
    __syncthreads();
    for (int r = w; r < MLPR; r += 8) {
        int pr = r >> 1, par = r & 1;
        float s = 0.f, s2 = 0.f;
        #pragma unroll
        for (int t = 0; t < 8; t++) {
            float v = hb[((size_t)pr * HID + lane + t * 32) * 2 + par];
            s += v; s2 += v * v;
        }
        s = wredsum(s); s2 = wredsum(s2);
        if (lane == 0) {
            float m = s * (1.f / HID);
            mu[r] = m;
            rsd[r] = rsqrtf(s2 * (1.f / HID) - m * m + 1e-5f);
        }
    }
    __syncthreads();
    {
        float4 gv = ((const float4*)g1)[c4], bev = ((const float4*)be1)[c4];
        float ga[4] = {gv.x, gv.y, gv.z, gv.w}, ba[4] = {bev.x, bev.y, bev.z, bev.w};
        #pragma unroll
        for (int rp = 0; rp < 4; rp++) {
            int pr = pbase + rp;
            float m0 = mu[2*pr], m1 = mu[2*pr+1], r0 = rsd[2*pr], r1 = rsd[2*pr+1];
            #pragma unroll
            for (int c = 0; c < 4; c++) {
                float lo, hi; up2(acc[c][rp], lo, hi);
                float h0 = (lo - m0) * r0 * ga[c] + ba[c];
                float h1 = (hi - m1) * r1 * ga[c] + ba[c];
                h0 = h0 > 0.f ? h0 : 0.01f * h0;
                h1 = h1 > 0.f ? h1 : 0.01f * h1;
                hbp[(size_t)pr * HID + 4 * c4 + c] = pk2(h0, h1);
            }
        }
    }
    __syncthreads();

    // ---- layer 2 ----
    gemm_panels4<HID>(g_W2U, hb, wp, wp_s32, ((const float4*)b2)[c4], acc, c4, pbase, tid);
    __syncthreads();   // hb reads done before overwrite
    #pragma unroll
    for (int rp = 0; rp < 4; rp++)
        #pragma unroll
        for (int c = 0; c < 4; c++)
            hbp[(size_t)(pbase + rp) * HID + 4 * c4 + c] = acc[c][rp];
    __syncthreads();
    for (int r = w; r < MLPR; r += 8) {
        int pr = r >> 1, par = r & 1;
        float s = 0.f, s2 = 0.f;
        #pragma unroll
        for (int t = 0; t < 8; t++) {
            float v = hb[((size_t)pr * HID + lane + t * 32) * 2 + par];
            s += v; s2 += v * v;
        }
        s = wredsum(s); s2 = wredsum(s2);
        if (lane == 0) {
            float m = s * (1.f / HID);
            mu[r] = m;
            rsd[r] = rsqrtf(s2 * (1.f / HID) - m * m + 1e-5f);
        }
    }
    __syncthreads();
    {
        float4 gv = ((const float4*)g2)[c4], bev = ((const float4*)be2)[c4];
        float ga[4] = {gv.x, gv.y, gv.z, gv.w}, ba[4] = {bev.x, bev.y, bev.z, bev.w};
        #pragma unroll
        for (int rp = 0; rp < 4; rp++) {
            int pr = pbase + rp;
            float m0 = mu[2*pr], m1 = mu[2*pr+1], r0 = rsd[2*pr], r1 = rsd[2*pr+1];
            #pragma unroll
            for (int c = 0; c < 4; c++) {
                float lo, hi; up2(acc[c][rp], lo, hi);
                float w3c = w3s[4 * c4 + c];
                float h0 = (lo - m0) * r0 * ga[c] + ba[c];
                float h1 = (hi - m1) * r1 * ga[c] + ba[c];
                h0 = h0 > 0.f ? h0 : 0.01f * h0;
                h1 = h1 > 0.f ? h1 : 0.01f * h1;
                hbp[(size_t)pr * HID + 4 * c4 + c] = pk2(h0 * w3c, h1 * w3c);
            }
        }
    }
    __syncthreads();
    float b3v = b3[0];
    for (int r = w; r < MLPR; r += 8) {
        int pr = r >> 1, par = r & 1;
        float s = 0.f;
        #pragma unroll
        for (int t = 0; t < 8; t++)
            s += hb[((size_t)pr * HID + lane + t * 32) * 2 + par];
        s = wredsum(s);
        if (lane == 0) {
            float yv = s + b3v;
            g_conc[row0 + r] = (yv > 20.f) ? yv : log1pf(expf(yv));
        }
    }
}

// ---------------- final normalize per batch ----------------
__global__ __launch_bounds__(128) void final_kernel(float* __restrict__ out) {
    __shared__ float sb[4];
    int b = blockIdx.x, tid = threadIdx.x, lane = tid & 31, w = tid >> 5;
    float v = (tid < NNODE) ? g_conc[b * NNODE + tid] : 0.f;
    float s = v;
    #pragma unroll
    for (int o = 16; o; o >>= 1) s += __shfl_xor_sync(0xffffffffu, s, o);
    if (lane == 0) sb[w] = s;
    __syncthreads();
    float tt = sb[0] + sb[1] + sb[2] + sb[3];
    if (tid < NNODE) out[b * NNODE + tid] = v / (tt + 1e-20f);
}

// ---------------- launch ----------------
extern "C" void kernel_launch(void* const* d_in, const int* in_sizes, int n_in,
                              void* d_out, int out_size) {
    const float* state = (const float*)d_in[0];
    const float* pos   = (const float*)d_in[1];
    const float* ew    = (const float*)d_in[2];
    const float* Wq  = (const float*)d_in[3];  const float* bq  = (const float*)d_in[4];
    const float* Wk  = (const float*)d_in[5];  const float* bk  = (const float*)d_in[6];
    const float* Wv  = (const float*)d_in[7];  const float* bv  = (const float*)d_in[8];
    const float* We  = (const float*)d_in[9];
    const float* Wsk = (const float*)d_in[10]; const float* bsk = (const float*)d_in[11];
    const float* W1  = (const float*)d_in[12]; const float* b1  = (const float*)d_in[13];
    const float* g1  = (const float*)d_in[14]; const float* be1 = (const float*)d_in[15];
    const float* W2  = (const float*)d_in[16]; const float* b2  = (const float*)d_in[17];
    const float* g2  = (const float*)d_in[18]; const float* be2 = (const float*)d_in[19];
    const float* W3  = (const float*)d_in[20]; const float* b3  = (const float*)d_in[21];
    const int*   ei  = (const int*)d_in[22];
    float* out = (float*)d_out;

    cudaFuncSetAttribute(edge_kernel, cudaFuncAttributeMaxDynamicSharedMemorySize, EDGE_SMEM_BYTES);
    cudaFuncSetAttribute(mlp_kernel,  cudaFuncAttributeMaxDynamicSharedMemorySize, MLP_SMEM_BYTES);

    prep_sort<<<1, 256>>>(ei, ew);                                     // 1
    prep_weights<<<180, 256>>>(Wq, Wk, Wv, Wsk, W1, W2);               // 2
    qkvs_kernel<<<NROWS / MROWS, 256>>>(state, pos, bq, bk, bv, bsk);  // 3
    edge_kernel<<<BATCH, ETHR, EDGE_SMEM_BYTES>>>(state, pos, We);     // 4 (profiled)
    mlp_kernel<<<NROWS / MLPR, 256, MLP_SMEM_BYTES>>>(b1, g1, be1, b2, g2, be2, W3, b3); // 5
    final_kernel<<<BATCH, 128>>>(out);                                 // 6
}

// round 17
// speedup vs baseline: 1.0530x; 1.0308x over previous
#include <cuda_runtime.h>
#include <cstdint>

typedef unsigned long long ull;

#define BATCH 256
#define NNODE 79
#define HID 256
#define NEDGE 3000
#define KP1 104
#define NROWS (BATCH*NNODE)     // 20224
#define MROWS 64                // qkvs rows/CTA
#define MLPR 32                 // mlp rows/CTA
#define ETHR 768                // edge threads/CTA
#define NCH 24
#define CHSZ 125
#define NCELL (NNODE*NCH)

// ---------------- device scratch ----------------
__device__ int   g_srcp[NEDGE];
__device__ float g_ewp[NEDGE];
__device__ int   g_rowptr[NNODE + 1];
__device__ ull   g_W4D[32 * 256];
__device__ float g_W1U[KP1 * HID];
__device__ float g_W2U[HID * HID];
__device__ float g_q[(size_t)NROWS * 64];
__device__ float g_k[(size_t)NROWS * 64];
__device__ float g_v[(size_t)NROWS * 64];
__device__ float g_hin[(size_t)NROWS * KP1];
__device__ float g_conc[NROWS];

__device__ __forceinline__ float wredsum(float v) {
    #pragma unroll
    for (int o = 16; o; o >>= 1) v += __shfl_xor_sync(0xffffffffu, v, o);
    return v;
}
__device__ __forceinline__ float wredmax(float v) {
    #pragma unroll
    for (int o = 16; o; o >>= 1) v = fmaxf(v, __shfl_xor_sync(0xffffffffu, v, o));
    return v;
}
__device__ __forceinline__ ull dup2(float v) {
    ull r; asm("mov.b64 %0,{%1,%1};" : "=l"(r) : "f"(v)); return r;
}
__device__ __forceinline__ ull pk2(float a, float b) {
    ull r; asm("mov.b64 %0,{%1,%2};" : "=l"(r) : "f"(a), "f"(b)); return r;
}
__device__ __forceinline__ ull f2fma(ull a, ull b, ull c) {
    ull d; asm("fma.rn.f32x2 %0,%1,%2,%3;" : "=l"(d) : "l"(a), "l"(b), "l"(c)); return d;
}
__device__ __forceinline__ ull f2add(ull a, ull b) {
    ull d; asm("add.rn.f32x2 %0,%1,%2;" : "=l"(d) : "l"(a), "l"(b)); return d;
}
__device__ __forceinline__ ull f2mul(ull a, ull b) {
    ull d; asm("mul.rn.f32x2 %0,%1,%2;" : "=l"(d) : "l"(a), "l"(b)); return d;
}
__device__ __forceinline__ void up2(ull v, float& lo, float& hi) {
    asm("mov.b64 {%0,%1},%2;" : "=f"(lo), "=f"(hi) : "l"(v));
}
__device__ __forceinline__ ull f2shflx(ull v, int m) {
    float lo, hi; up2(v, lo, hi);
    lo = __shfl_xor_sync(0xffffffffu, lo, m);
    hi = __shfl_xor_sync(0xffffffffu, hi, m);
    return pk2(lo, hi);
}
__device__ __forceinline__ void cpasync16(uint32_t saddr, const float* g) {
    asm volatile("cp.async.ca.shared.global [%0], [%1], 16;" :: "r"(saddr), "l"(g));
}

// ---------------- prep: block0 = CSR sort; blocks 1.. = weight transposes ----------------
__global__ __launch_bounds__(256) void prep_kernel(
    const int* __restrict__ ei, const float* __restrict__ ew,
    const float* __restrict__ Wq, const float* __restrict__ Wk,
    const float* __restrict__ Wv, const float* __restrict__ Wsk,
    const float* __restrict__ W1, const float* __restrict__ W2) {
    int tid = threadIdx.x;
    if (blockIdx.x == 0) {
        __shared__ int dsts[NEDGE];
        __shared__ int cell[NCELL];
        __shared__ int wsum[8];
        int lane = tid & 31, w = tid >> 5;
        for (int e = tid; e < NEDGE; e += 256) dsts[e] = ei[NEDGE + e];
        for (int c = tid; c < NCELL; c += 256) cell[c] = 0;
        __syncthreads();
        for (int e = tid; e < NEDGE; e += 256)
            atomicAdd(&cell[dsts[e] * NCH + e / CHSZ], 1);
        __syncthreads();
        int base = tid * 8, loc[8], s = 0;
        #pragma unroll
        for (int j = 0; j < 8; j++) {
            int v = (base + j < NCELL) ? cell[base + j] : 0;
            loc[j] = s; s += v;
        }
        int x = s;
        #pragma unroll
        for (int o = 1; o < 32; o <<= 1) {
            int t = __shfl_up_sync(0xffffffffu, x, o);
            if (lane >= o) x += t;
        }
        if (lane == 31) wsum[w] = x;
        int exw = x - s;
        __syncthreads();
        if (tid == 0) {
            int a = 0;
            for (int i = 0; i < 8; i++) { int t = wsum[i]; wsum[i] = a; a += t; }
        }
        __syncthreads();
        int off = wsum[w] + exw;
        #pragma unroll
        for (int j = 0; j < 8; j++) if (base + j < NCELL) cell[base + j] = off + loc[j];
        __syncthreads();
        if (tid < NNODE) g_rowptr[tid] = cell[tid * NCH];
        if (tid == 0) g_rowptr[NNODE] = NEDGE;
        for (int e = tid; e < NEDGE; e += 256) {
            int d = dsts[e];
            int ch = e / CHSZ, b0 = ch * CHSZ;
            int rank = 0;
            for (int e2 = b0; e2 < e; e2++) rank += (dsts[e2] == d);
            int pos = cell[d * NCH + ch] + rank;
            g_srcp[pos] = ei[e]; g_ewp[pos] = ew[e];
        }
    } else {
        int gtid = (blockIdx.x - 1) * 256 + tid, gs = (gridDim.x - 1) * 256;
        for (int t = gtid; t < 32 * 256; t += gs) {
            int k = t >> 8, ch = t & 255;
            float v;
            if (ch < 64)       v = Wq[ch * 32 + k];
            else if (ch < 128) v = Wk[(ch - 64) * 32 + k];
            else if (ch < 192) v = Wv[(ch - 128) * 32 + k];
            else               v = Wsk[(ch - 192) * 32 + k];
            g_W4D[t] = pk2(v, v);
        }
        for (int t = gtid; t < KP1 * HID; t += gs) {
            int k = t >> 8, j = t & 255;
            g_W1U[t] = (k < 97) ? W1[j * 97 + k] : 0.f;
        }
        for (int t = gtid; t < HID * HID; t += gs) {
            int k = t >> 8, j = t & 255;
            g_W2U[t] = W2[j * HID + k];
        }
    }
}

// ---------------- gemm engines ----------------
template<int K>
__device__ __forceinline__ void gemm_reg(const ull* __restrict__ Wg,
                                         const float* __restrict__ xsrc,
                                         float4 bvv, ull (&acc)[4][8],
                                         int c4, int pbase) {
    #pragma unroll
    for (int rp = 0; rp < 8; rp++) {
        acc[0][rp] = dup2(bvv.x); acc[1][rp] = dup2(bvv.y);
        acc[2][rp] = dup2(bvv.z); acc[3][rp] = dup2(bvv.w);
    }
    const float* xb = xsrc + (size_t)pbase * K * 2;
    const ull* wb = Wg + 4 * c4;
    #pragma unroll 2
    for (int k = 0; k < K; k += 2) {
        ulonglong2 w0a = __ldg((const ulonglong2*)(wb + (size_t)k * 256));
        ulonglong2 w0b = __ldg((const ulonglong2*)(wb + (size_t)k * 256 + 2));
        ulonglong2 w1a = __ldg((const ulonglong2*)(wb + (size_t)(k + 1) * 256));
        ulonglong2 w1b = __ldg((const ulonglong2*)(wb + (size_t)(k + 1) * 256 + 2));
        #pragma unroll
        for (int rp = 0; rp < 8; rp++) {
            ulonglong2 xv = *(const ulonglong2*)(xb + ((size_t)rp * K + k) * 2);
            acc[0][rp] = f2fma(xv.x, w0a.x, acc[0][rp]);
            acc[1][rp] = f2fma(xv.x, w0a.y, acc[1][rp]);
            acc[2][rp] = f2fma(xv.x, w0b.x, acc[2][rp]);
            acc[3][rp] = f2fma(xv.x, w0b.y, acc[3][rp]);
            acc[0][rp] = f2fma(xv.y, w1a.x, acc[0][rp]);
            acc[1][rp] = f2fma(xv.y, w1a.y, acc[1][rp]);
            acc[2][rp] = f2fma(xv.y, w1b.x, acc[2][rp]);
            acc[3][rp] = f2fma(xv.y, w1b.y, acc[3][rp]);
        }
    }
}

// quad-buffered smem k-panels, ONE syncthreads per panel, 4ch x 4 row-pairs
// NOTE: caller must __syncthreads() after return before reusing smem aliased with xsrc.
template<int K>
__device__ __forceinline__ void gemm_panels4(const float* __restrict__ Wg,
                                             const float* __restrict__ xsrc,
                                             float* __restrict__ wp, uint32_t wp_s32,
                                             float4 bvv, ull (&acc)[4][4],
                                             int c4, int pbase, int tid) {
    const int NP = K / 8;
    #pragma unroll
    for (int p = 0; p < 3; p++) {
        uint32_t dst = wp_s32 + p * 8192;
        cpasync16(dst + tid * 16, Wg + p * 2048 + tid * 4);
        cpasync16(dst + 4096 + tid * 16, Wg + p * 2048 + 1024 + tid * 4);
        asm volatile("cp.async.commit_group;");
    }
    #pragma unroll
    for (int rp = 0; rp < 4; rp++) {
        acc[0][rp] = dup2(bvv.x); acc[1][rp] = dup2(bvv.y);
        acc[2][rp] = dup2(bvv.z); acc[3][rp] = dup2(bvv.w);
    }
    const float* xb = xsrc + (size_t)pbase * K * 2;
    #pragma unroll 1
    for (int p = 0; p < NP; p++) {
        asm volatile("cp.async.wait_group 2;");
        __syncthreads();
        if (p + 3 < NP) {
            uint32_t dst = wp_s32 + ((p + 3) & 3) * 8192;
            cpasync16(dst + tid * 16, Wg + (p + 3) * 2048 + tid * 4);
            cpasync16(dst + 4096 + tid * 16, Wg + (p + 3) * 2048 + 1024 + tid * 4);
        }
        asm volatile("cp.async.commit_group;");
        const float* wb = wp + (p & 3) * 2048;
        #pragma unroll
        for (int kk2 = 0; kk2 < 4; kk2++) {
            int kl = kk2 * 2;
            float4 wa = *(const float4*)(wb + kl * 256 + 4 * c4);
            float4 wc = *(const float4*)(wb + (kl + 1) * 256 + 4 * c4);
            ull a0 = dup2(wa.x), a1 = dup2(wa.y), a2 = dup2(wa.z), a3 = dup2(wa.w);
            ull c0 = dup2(wc.x), c1 = dup2(wc.y), c2 = dup2(wc.z), c3 = dup2(wc.w);
            int kg = p * 8 + kl;
            #pragma unroll
            for (int rp = 0; rp < 4; rp++) {
                ulonglong2 xv = *(const ulonglong2*)(xb + ((size_t)rp * K + kg) * 2);
                acc[0][rp] = f2fma(xv.x, a0, acc[0][rp]);
                acc[1][rp] = f2fma(xv.x, a1, acc[1][rp]);
                acc[2][rp] = f2fma(xv.x, a2, acc[2][rp]);
                acc[3][rp] = f2fma(xv.x, a3, acc[3][rp]);
                acc[0][rp] = f2fma(xv.y, c0, acc[0][rp]);
                acc[1][rp] = f2fma(xv.y, c1, acc[1][rp]);
                acc[2][rp] = f2fma(xv.y, c2, acc[2][rp]);
                acc[3][rp] = f2fma(xv.y, c3, acc[3][rp]);
            }
        }
    }
}

// ---------------- qkvs ----------------
__global__ __launch_bounds__(256, 2) void qkvs_kernel(
    const float* __restrict__ state, const float* __restrict__ pos,
    const float* __restrict__ bq, const float* __restrict__ bk,
    const float* __restrict__ bv, const float* __restrict__ bsk) {
    __shared__ float xs[2048];
    __shared__ float bias[256];
    int tid = threadIdx.x;
    int c4 = tid & 63, pbase = (tid >> 6) * 8;
    size_t row0 = (size_t)blockIdx.x * MROWS;

    for (int idx = tid; idx < MROWS * 32; idx += 256) {
        int r = idx >> 5, k = idx & 31;
        size_t g = row0 + r;
        int node = (int)(g % NNODE);
        float v = (k < 26) ? state[g * 26 + k] : pos[node * 6 + (k - 26)];
        xs[((r >> 1) * 32 + k) * 2 + (r & 1)] = v;
    }
    {
        int ch = tid;
        float v = (ch < 64) ? bq[ch] : (ch < 128) ? bk[ch - 64]
                : (ch < 192) ? bv[ch - 128] : bsk[ch - 192];
        bias[ch] = v;
    }
    __syncthreads();

    ull acc[4][8];
    gemm_reg<32>(g_W4D, xs, ((const float4*)bias)[c4], acc, c4, pbase);

    int sect = c4 >> 4;
    int ch4 = (c4 & 15) * 4;
    #pragma unroll
    for (int rp = 0; rp < 8; rp++) {
        float l0, h0, l1, h1, l2, h2, l3, h3;
        up2(acc[0][rp], l0, h0); up2(acc[1][rp], l1, h1);
        up2(acc[2][rp], l2, h2); up2(acc[3][rp], l3, h3);
        float4 ev = make_float4(l0, l1, l2, l3);
        float4 ov = make_float4(h0, h1, h2, h3);
        size_t g0 = row0 + 2 * (pbase + rp), g1 = g0 + 1;
        if (sect == 0) {
            *(float4*)(g_q + g0 * 64 + ch4) = ev;
            *(float4*)(g_q + g1 * 64 + ch4) = ov;
        } else if (sect == 1) {
            *(float4*)(g_k + g0 * 64 + ch4) = ev;
            *(float4*)(g_k + g1 * 64 + ch4) = ov;
        } else if (sect == 2) {
            *(float4*)(g_v + g0 * 64 + ch4) = ev;
            *(float4*)(g_v + g1 * 64 + ch4) = ov;
        } else {
            *(float4*)(g_hin + g0 * KP1 + ch4) = ev;
            *(float4*)(g_hin + g1 * KP1 + ch4) = ov;
        }
    }
}

// ---------------- edge: per-batch attention, 768 threads ----------------
#define EDGE_SMEM_FLOATS (3*5372 + 3000 + 80 + 64 + 4 + 80 + 80 + 1500)
#define EDGE_SMEM_BYTES  (EDGE_SMEM_FLOATS * 4)

__global__ __launch_bounds__(ETHR) void edge_kernel(
    const float* __restrict__ state, const float* __restrict__ pos,
    const float* __restrict__ We) {
    extern __shared__ float sm[];
    float* qs  = sm;
    float* ks  = qs + 5372;
    float* vs  = ks + 5372;
    float* alp = vs + 5372;
    float* qWe = alp + 3000;
    float* wes = qWe + 80;
    float* tot = wes + 64;
    int*   rps = (int*)(tot + 4);
    float* sx  = (float*)(rps + 80);
    short* srcp_s = (short*)(sx + 80);

    int b = blockIdx.x, tid = threadIdx.x, lane = tid & 31, w = tid >> 5;
    size_t base = (size_t)b * NNODE;

    for (int idx = tid; idx < NNODE * 16; idx += ETHR) {
        int row = idx >> 4, f4 = idx & 15;
        float4 qv = __ldg(((const float4*)(g_q + (base + row) * 64)) + f4);
        float4 kv = __ldg(((const float4*)(g_k + (base + row) * 64)) + f4);
        float4 vv = __ldg(((const float4*)(g_v + (base + row) * 64)) + f4);
        *(float4*)(qs + row * 68 + f4 * 4) = qv;
        *(float4*)(ks + row * 68 + f4 * 4) = kv;
        *(float4*)(vs + row * 68 + f4 * 4) = vv;
    }
    for (int e = tid; e < NEDGE; e += ETHR) srcp_s[e] = (short)g_srcp[e];
    if (tid <= NNODE) rps[tid] = g_rowptr[tid];
    if (tid >= 128 && tid < 192) wes[tid - 128] = We[tid - 128];
    if (tid >= 256 && tid < 256 + NNODE) sx[tid - 256] = __ldg(state + (base + tid - 256) * 26 + 1);
    __syncthreads();

    if (w == 0) {
        float s = 0.f;
        for (int j = lane; j < NNODE; j += 32) s += sx[j];
        s = wredsum(s);
        if (lane == 0) tot[0] = s;
    }
    if (tid < NNODE) {
        float a = 0.f;
        const float* qr = qs + tid * 68;
        #pragma unroll 8
        for (int d = 0; d < 64; d++) a += qr[d] * wes[d];
        qWe[tid] = a;
    }
    __syncthreads();

    {
        int g = lane >> 3, li = lane & 7;
        for (int i = w; i < NNODE; i += 24) {
            int s0 = rps[i], e1 = rps[i + 1];
            const float4* qr = (const float4*)(qs + i * 68 + li * 8);
            float4 q0 = qr[0], q1 = qr[1];
            float qwei = qWe[i];
            #pragma unroll 1
            for (int eb = s0; eb < e1; eb += 4) {
                int e = eb + g;
                bool valid = e < e1;
                int ec = valid ? e : e1 - 1;
                int ss = srcp_s[ec];
                float ewv = __ldg(g_ewp + ec);
                const float4* kr = (const float4*)(ks + ss * 68 + li * 8);
                float4 k0 = kr[0], k1 = kr[1];
                float p = q0.x*k0.x + q0.y*k0.y + q0.z*k0.z + q0.w*k0.w
                        + q1.x*k1.x + q1.y*k1.y + q1.z*k1.z + q1.w*k1.w;
                p += __shfl_xor_sync(0xffffffffu, p, 1);
                p += __shfl_xor_sync(0xffffffffu, p, 2);
                p += __shfl_xor_sync(0xffffffffu, p, 4);
                if (li == 0 && valid) alp[e] = 0.125f * (p + ewv * qwei);
            }
        }
    }
    for (int idx = tid; idx < NNODE * 40; idx += ETHR) {
        int i = idx / 40, c = idx - i * 40;
        float v;
        if (c == 0) v = tot[0];
        else if (c <= 26) v = __ldg(state + (base + i) * 26 + (c - 1));
        else if (c <= 32) v = __ldg(pos + i * 6 + (c - 27));
        else v = 0.f;
        g_hin[(base + i) * KP1 + 64 + c] = v;
    }
    __syncthreads();

    float we0 = wes[lane], we1 = wes[lane + 32];
    for (int i = w; i < NNODE; i += 24) {
        int s0 = rps[i], e1 = rps[i + 1];
        float a0 = 0.f, a1 = 0.f;
        if (e1 > s0) {
            float m = -1e30f;
            for (int e = s0 + lane; e < e1; e += 32) m = fmaxf(m, alp[e]);
            m = wredmax(m);
            float den = 0.f, sew = 0.f;
            for (int e = s0 + lane; e < e1; e += 32) {
                float ex = __expf(alp[e] - m);
                alp[e] = ex; den += ex; sew += ex * __ldg(g_ewp + e);
            }
            den = wredsum(den); sew = wredsum(sew);
            float inv = 1.f / (den + 1e-16f);
            float b0 = 0.f, b1 = 0.f;
            int e = s0;
            #pragma unroll 1
            for (; e + 1 < e1; e += 2) {
                float w0 = alp[e], w1v = alp[e + 1];
                int sA = srcp_s[e], sB = srcp_s[e + 1];
                a0 += w0 * vs[sA * 68 + lane];
                a1 += w0 * vs[sA * 68 + lane + 32];
                b0 += w1v * vs[sB * 68 + lane];
                b1 += w1v * vs[sB * 68 + lane + 32];
            }
            if (e < e1) {
                float w0 = alp[e]; int sA = srcp_s[e];
                a0 += w0 * vs[sA * 68 + lane];
                a1 += w0 * vs[sA * 68 + lane + 32];
            }
            a0 = (a0 + b0 + sew * we0) * inv;
            a1 = (a1 + b1 + sew * we1) * inv;
        }
        size_t r = base + i;
        float s0v = g_hin[r * KP1 + lane];
        float s1v = g_hin[r * KP1 + lane + 32];
        g_hin[r * KP1 + lane]      = fmaxf(a0 + s0v, 0.f);
        g_hin[r * KP1 + lane + 32] = fmaxf(a1 + s1v, 0.f);
    }
}

// ---------------- MLP: register-resident LN + fused head ----------------
// smem floats: wp 8192 | buf 8192 (xs alias + hb) | pst 96 ull (192) | w3s 256
#define MLP_SMEM_FLOATS (8192 + 8192 + 192 + 256)
#define MLP_SMEM_BYTES  (MLP_SMEM_FLOATS * 4)

__global__ __launch_bounds__(256, 3) void mlp_kernel(
    const float* __restrict__ b1, const float* __restrict__ g1, const float* __restrict__ be1,
    const float* __restrict__ b2, const float* __restrict__ g2, const float* __restrict__ be2,
    const float* __restrict__ W3, const float* __restrict__ b3) {
    extern __shared__ float sm[];
    float* wp  = sm;                  // 4 x 8 x 256 weight panels
    float* buf = sm + 8192;           // xs (first 3328) aliased with hb (8192)
    float* xs  = buf;
    float* hb  = buf;
    ull*   pst = (ull*)(buf + 8192);  // 96 ull: [0..63] stats, [64..95] head partials
    float* w3s = (float*)(pst + 96);  // 256
    ull* hbp = (ull*)hb;
    uint32_t wp_s32 = (uint32_t)__cvta_generic_to_shared(wp);
    int tid = threadIdx.x, lane = tid & 31, w = tid >> 5;
    int c4 = tid & 63, pbase = (tid >> 6) * 4;
    size_t row0 = (size_t)blockIdx.x * MLPR;

    {
        const float4* src4 = (const float4*)(g_hin + row0 * KP1);
        for (int i = tid; i < MLPR * 26; i += 256) {
            int r = i / 26, q = i - r * 26;
            float4 f = src4[i];
            float* d = xs + ((r >> 1) * KP1 + 4 * q) * 2 + (r & 1);
            d[0] = f.x; d[2] = f.y; d[4] = f.z; d[6] = f.w;
        }
    }
    w3s[tid] = W3[tid];
    __syncthreads();

    ull acc[4][4];
    // ---- layer 1 ----
    gemm_panels4<KP1>(g_W1U, xs, wp, wp_s32, ((const float4*)b1)[c4], acc, c4, pbase, tid);
    // register LN stats: per row-pair, sum & sumsq over this thread's 4 channels,
    // reduce over warp (128 ch), exchange with partner warp (256 ch)
    #pragma unroll
    for (int rp = 0; rp < 4; rp++) {
        ull s  = f2add(f2add(acc[0][rp], acc[1][rp]), f2add(acc[2][rp], acc[3][rp]));
        ull s2 = f2fma(acc[0][rp], acc[0][rp],
                 f2fma(acc[1][rp], acc[1][rp],
                 f2fma(acc[2][rp], acc[2][rp], f2mul(acc[3][rp], acc[3][rp]))));
        #pragma unroll
        for (int m = 16; m; m >>= 1) {
            s  = f2add(s,  f2shflx(s,  m));
            s2 = f2add(s2, f2shflx(s2, m));
        }
        if (lane == 0) { pst[w * 8 + rp] = s; pst[w * 8 + 4 + rp] = s2; }
    }
    __syncthreads();   // stats visible; also fences xs reads before hb (alias) writes
    {
        float4 gv = ((const float4*)g1)[c4], bev = ((const float4*)be1)[c4];
        float ga[4] = {gv.x, gv.y, gv.z, gv.w}, ba[4] = {bev.x, bev.y, bev.z, bev.w};
        int ow = w * 8, pw = (w ^ 1) * 8;
        #pragma unroll
        for (int rp = 0; rp < 4; rp++) {
            ull ts = f2add(pst[ow + rp], pst[pw + rp]);
            ull t2 = f2add(pst[ow + 4 + rp], pst[pw + 4 + rp]);
            float slo, shi, qlo, qhi;
            up2(ts, slo, shi); up2(t2, qlo, qhi);
            float m0 = slo * (1.f / HID), m1 = shi * (1.f / HID);
            float r0 = rsqrtf(qlo * (1.f / HID) - m0 * m0 + 1e-5f);
            float r1 = rsqrtf(qhi * (1.f / HID) - m1 * m1 + 1e-5f);
            int pr = pbase + rp;
            #pragma unroll
            for (int c = 0; c < 4; c++) {
                float lo, hi; up2(acc[c][rp], lo, hi);
                float h0 = (lo - m0) * r0 * ga[c] + ba[c];
                float h1 = (hi - m1) * r1 * ga[c] + ba[c];
                h0 = fmaxf(h0, 0.01f * h0);
                h1 = fmaxf(h1, 0.01f * h1);
                hbp[(size_t)pr * HID + 4 * c4 + c] = pk2(h0, h1);
            }
        }
    }
    __syncthreads();

    // ---- layer 2 + fused LN + head ----
    gemm_panels4<HID>(g_W2U, hb, wp, wp_s32, ((const float4*)b2)[c4], acc, c4, pbase, tid);
    #pragma unroll
    for (int rp = 0; rp < 4; rp++) {
        ull s  = f2add(f2add(acc[0][rp], acc[1][rp]), f2add(acc[2][rp], acc[3][rp]));
        ull s2 = f2fma(acc[0][rp], acc[0][rp],
                 f2fma(acc[1][rp], acc[1][rp],
                 f2fma(acc[2][rp], acc[2][rp], f2mul(acc[3][rp], acc[3][rp]))));
        #pragma unroll
        for (int m = 16; m; m >>= 1) {
            s  = f2add(s,  f2shflx(s,  m));
            s2 = f2add(s2, f2shflx(s2, m));
        }
        if (lane == 0) { pst[w * 8 + rp] = s; pst[w * 8 + 4 + rp] = s2; }
    }
    __syncthreads();
    ull os[4];
    {
        float4 gv = ((const float4*)g2)[c4], bev = ((const float4*)be2)[c4];
        float ga[4] = {gv.x, gv.y, gv.z, gv.w}, ba[4] = {bev.x, bev.y, bev.z, bev.w};
        float w3a[4] = {w3s[4 * c4], w3s[4 * c4 + 1], w3s[4 * c4 + 2], w3s[4 * c4 + 3]};
        int ow = w * 8, pw = (w ^ 1) * 8;
        #pragma unroll
        for (int rp = 0; rp < 4; rp++) {
            ull ts = f2add(pst[ow + rp], pst[pw + rp]);
            ull t2 = f2add(pst[ow + 4 + rp], pst[pw + 4 + rp]);
            float slo, shi, qlo, qhi;
            up2(ts, slo, shi); up2(t2, qlo, qhi);
            float m0 = slo * (1.f / HID), m1 = shi * (1.f / HID);
            float r0 = rsqrtf(qlo * (1.f / HID) - m0 * m0 + 1e-5f);
            float r1 = rsqrtf(qhi * (1.f / HID) - m1 * m1 + 1e-5f);
            float o0 = 0.f, o1 = 0.f;
            #pragma unroll
            for (int c = 0; c < 4; c++) {
                float lo, hi; up2(acc[c][rp], lo, hi);
                float h0 = (lo - m0) * r0 * ga[c] + ba[c];
                float h1 = (hi - m1) * r1 * ga[c] + ba[c];
                h0 = fmaxf(h0, 0.01f * h0);
                h1 = fmaxf(h1, 0.01f * h1);
                o0 += h0 * w3a[c]; o1 += h1 * w3a[c];
            }
            ull o = pk2(o0, o1);
            #pragma unroll
            for (int m = 16; m; m >>= 1) o = f2add(o, f2shflx(o, m));
            os[rp] = o;
        }
    }
    if (lane == 0) {
        #pragma unroll
        for (int rp = 0; rp < 4; rp++) pst[64 + w * 4 + rp] = os[rp];
    }
    __syncthreads();
    if ((w & 1) == 0 && lane == 0) {
        float b3v = b3[0];
        #pragma unroll
        for (int rp = 0; rp < 4; rp++) {
            ull t = f2add(os[rp], pst[64 + (w + 1) * 4 + rp]);
            float y0, y1; up2(t, y0, y1);
            y0 += b3v; y1 += b3v;
            y0 = (y0 > 20.f) ? y0 : log1pf(expf(y0));
            y1 = (y1 > 20.f) ? y1 : log1pf(expf(y1));
            int pr = pbase + rp;
            *(float2*)(g_conc + row0 + 2 * pr) = make_float2(y0, y1);
        }
    }
}

// ---------------- final normalize per batch ----------------
__global__ __launch_bounds__(128) void final_kernel(float* __restrict__ out) {
    __shared__ float sb[4];
    int b = blockIdx.x, tid = threadIdx.x, lane = tid & 31, w = tid >> 5;
    float v = (tid < NNODE) ? g_conc[b * NNODE + tid] : 0.f;
    float s = v;
    #pragma unroll
    for (int o = 16; o; o >>= 1) s += __shfl_xor_sync(0xffffffffu, s, o);
    if (lane == 0) sb[w] = s;
    __syncthreads();
    float tt = sb[0] + sb[1] + sb[2] + sb[3];
    if (tid < NNODE) out[b * NNODE + tid] = v / (tt + 1e-20f);
}

// ---------------- launch ----------------
extern "C" void kernel_launch(void* const* d_in, const int* in_sizes, int n_in,
                              void* d_out, int out_size) {
    const float* state = (const float*)d_in[0];
    const float* pos   = (const float*)d_in[1];
    const float* ew    = (const float*)d_in[2];
    const float* Wq  = (const float*)d_in[3];  const float* bq  = (const float*)d_in[4];
    const float* Wk  = (const float*)d_in[5];  const float* bk  = (const float*)d_in[6];
    const float* Wv  = (const float*)d_in[7];  const float* bv  = (const float*)d_in[8];
    const float* We  = (const float*)d_in[9];
    const float* Wsk = (const float*)d_in[10]; const float* bsk = (const float*)d_in[11];
    const float* W1  = (const float*)d_in[12]; const float* b1  = (const float*)d_in[13];
    const float* g1  = (const float*)d_in[14]; const float* be1 = (const float*)d_in[15];
    const float* W2  = (const float*)d_in[16]; const float* b2  = (const float*)d_in[17];
    const float* g2  = (const float*)d_in[18]; const float* be2 = (const float*)d_in[19];
    const float* W3  = (const float*)d_in[20]; const float* b3  = (const float*)d_in[21];
    const int*   ei  = (const int*)d_in[22];
    float* out = (float*)d_out;

    cudaFuncSetAttribute(edge_kernel, cudaFuncAttributeMaxDynamicSharedMemorySize, EDGE_SMEM_BYTES);
    cudaFuncSetAttribute(mlp_kernel,  cudaFuncAttributeMaxDynamicSharedMemorySize, MLP_SMEM_BYTES);

    prep_kernel<<<180, 256>>>(ei, ew, Wq, Wk, Wv, Wsk, W1, W2);        // 1
    qkvs_kernel<<<NROWS / MROWS, 256>>>(state, pos, bq, bk, bv, bsk);  // 2
    edge_kernel<<<BATCH, ETHR, EDGE_SMEM_BYTES>>>(state, pos, We);     // 3
    mlp_kernel<<<NROWS / MLPR, 256, MLP_SMEM_BYTES>>>(b1, g1, be1, b2, g2, be2, W3, b3); // 4 (profiled)
    final_kernel<<<BATCH, 128>>>(out);                                 // 5
}